// round 15
// baseline (speedup 1.0000x reference)
#include <cuda_runtime.h>
#include <cstdint>

#define NMAX 50000
#define EMAX 1000000
#define XS_P 132
#define TXP 68     // A-tile smem pitch (tf32 words)

// ---------------- scratch (static device globals; no allocation) ----------------
__device__ int      g_cntflag[NMAX + 64];        // deg counts + scan flags (re-zeroed by k_fill)
__device__ int      g_pref[64];
__device__ int      g_off[NMAX + 1];
__device__ int      g_cursor[NMAX];
__device__ float    g_rdeg[NMAX];
__device__ int2     g_erecR[EMAX];               // {src*1280 + (rel+1)*256, w_bits}  (xt byte offset)
__device__ int2     g_erecG[EMAX];               // {src*256, w_bits}                 (h byte offset)
__device__ float    g_xt[(size_t)NMAX * 320];    // fp32 transformed feats [W0 | Wr0..Wr3]
__device__ float    g_h[(size_t)NMAX * 64];      // fp32 hidden state (rgcn relu out)
__device__ float    g_h2[(size_t)NMAX * 64];     // layer-1 group output (was agg buffer)
__device__ unsigned g_wfrag[2 * 5 * 4096];       // tf32 frag-major weights (dense), both layers

// ---------------- packed fp32x2 helpers ----------------
__device__ __forceinline__ void fma2(unsigned long long &a, unsigned long long x, unsigned long long w) {
    asm("fma.rn.f32x2 %0, %1, %2, %0;" : "+l"(a) : "l"(x), "l"(w));
}
__device__ __forceinline__ unsigned long long pack2(float v) {
    unsigned long long r;
    asm("mov.b64 %0, {%1, %1};" : "=l"(r) : "f"(v));
    return r;
}
__device__ __forceinline__ float2 unpack2(unsigned long long a) {
    float2 f;
    asm("mov.b64 {%0, %1}, %2;" : "=f"(f.x), "=f"(f.y) : "l"(a));
    return f;
}
__device__ __forceinline__ unsigned f2tf32(float v) {
    unsigned r;
    asm("cvt.rna.tf32.f32 %0, %1;" : "=r"(r) : "f"(v));
    return r;
}

// ---------------- weight pre-conversion: fp32 [64][64] -> tf32 frag-major (dense) ----------------
extern "C" __global__ void k_wprep(const float* __restrict__ W01, const float* __restrict__ W1,
                                   const float* __restrict__ W02, const float* __restrict__ W2,
                                   unsigned* __restrict__ wfrag) {
    int i = blockIdx.x * blockDim.x + threadIdx.x;
    if (i >= 2 * 5 * 4096) return;
    int L = i / 20480;
    int rem = i - L * 20480;
    int p = rem >> 12, j = rem & 4095;
    const float* W0 = L ? W02 : W01;
    const float* Wr = L ? W2 : W1;
    float v = (p == 0) ? W0[j] : Wr[(p - 1) * 4096 + j];
    int k = j >> 6, n = j & 63;
    int s = k >> 3, kr = k & 7;
    int tig = kr & 3, c = kr >> 2;
    int nt = n >> 3, gid = n & 7;
    int lane = gid * 4 + tig;
    int dst = ((s * 8 + nt) << 6) + (lane << 1) + c;
    wfrag[L * 20480 + (p << 12) + dst] = f2tf32(v);
}

// ---------------- degree (2 edges/thread) ----------------
extern "C" __global__ void k_deg(const int* __restrict__ ei, int* __restrict__ cnt, int E) {
    int e2 = blockIdx.x * blockDim.x + threadIdx.x;
    int e = e2 * 2;
    if (e < E) {
        int2 d = *(const int2*)&ei[E + e];
        atomicAdd(&cnt[d.x], 1);
        if (e + 1 < E) atomicAdd(&cnt[d.y], 1);
    }
}

// ---------------- single-pass chained scan ----------------
extern "C" __global__ void __launch_bounds__(1024)
k_scanAll(const int* __restrict__ cnt, int* __restrict__ flag, int* __restrict__ pref,
          int* __restrict__ off, int* __restrict__ cursor, float* __restrict__ rdeg,
          int N, int E) {
    __shared__ int wsum[32];
    __shared__ int s_pref;
    int t = threadIdx.x, b = blockIdx.x, g = b * 1024 + t;
    int v = (g < N) ? cnt[g] : 0;
    int lane = t & 31, wid = t >> 5;
    int x = v;
    #pragma unroll
    for (int d = 1; d < 32; d <<= 1) {
        int y = __shfl_up_sync(0xFFFFFFFF, x, d);
        if (lane >= d) x += y;
    }
    if (lane == 31) wsum[wid] = x;
    __syncthreads();
    if (wid == 0) {
        int s = wsum[lane];
        #pragma unroll
        for (int d = 1; d < 32; d <<= 1) {
            int y = __shfl_up_sync(0xFFFFFFFF, s, d);
            if (lane >= d) s += y;
        }
        wsum[lane] = s;
    }
    __syncthreads();
    int incl = x + (wid > 0 ? wsum[wid - 1] : 0);
    if (t == 0) {
        int p = 0;
        if (b > 0) {
            while (atomicAdd(&flag[b - 1], 0) == 0) __nanosleep(40);
            __threadfence();
            p = pref[b - 1];
        }
        s_pref = p;
        pref[b] = p + wsum[31];
        __threadfence();
        atomicExch(&flag[b], 1);
    }
    __syncthreads();
    int base = s_pref;
    if (g < N) {
        int o = base + incl - v;
        off[g] = o;
        cursor[g] = o;
        rdeg[g] = 1.0f / (float)max(v, 1);
    }
    if (g == 0) off[N] = E;
}

// fill CSR edge records (both variants); re-zero cnt+flags for next replay
extern "C" __global__ void k_fill(const int* __restrict__ ei, const int* __restrict__ et,
                                  const float* __restrict__ ew, int* __restrict__ cursor,
                                  int2* __restrict__ erecR, int2* __restrict__ erecG,
                                  int* __restrict__ cntflag, int E) {
    int e = blockIdx.x * blockDim.x + threadIdx.x;
    if (e < NMAX + 64) cntflag[e] = 0;
    if (e >= E) return;
    int dst = ei[E + e];
    int s = ei[e];
    int wb = __float_as_int(ew[e]);
    int pos = atomicAdd(&cursor[dst], 1);
    erecR[pos] = make_int2(s * 1280 + ((et[e] + 1) << 8), wb);
    erecG[pos] = make_int2(s << 8, wb);
}

// ---------------- transform (tf32 mma, cp.async double-buffered dense frag-major W) ----------------
extern "C" __global__ void __launch_bounds__(256)
k_transform_mma(const float* __restrict__ A, const unsigned* __restrict__ wfrag,
                float* __restrict__ out, int N) {
    extern __shared__ unsigned usm[];
    unsigned* xs = usm;               // [128][TXP]
    unsigned* wsb = usm + 128 * TXP;  // 2 x 4096
    int t = threadIdx.x;
    int r0 = blockIdx.x * 128;

    {
        unsigned sdst = (unsigned)__cvta_generic_to_shared(&wsb[t * 4]);
        const unsigned* gsrc = wfrag + t * 4;
        #pragma unroll
        for (int c = 0; c < 4; c++) {
            asm volatile("cp.async.cg.shared.global [%0], [%1], 16;"
                         :: "r"(sdst + c * 4096), "l"(gsrc + c * 1024));
        }
        asm volatile("cp.async.commit_group;");
    }

    for (int i = t; i < 128 * 16; i += 256) {
        int row = i >> 4, c4 = (i & 15) << 2;
        int g = r0 + row;
        float4 v = {0.f, 0.f, 0.f, 0.f};
        if (g < N) v = *(const float4*)&A[(size_t)g * 64 + c4];
        uint4 o;
        o.x = f2tf32(v.x); o.y = f2tf32(v.y); o.z = f2tf32(v.z); o.w = f2tf32(v.w);
        *(uint4*)&xs[row * TXP + c4] = o;
    }
    __syncthreads();

    int w = t >> 5, lane = t & 31;
    int gid = lane >> 2, tig = lane & 3;
    int arow = 16 * w + gid;

    unsigned a[8][4];
    #pragma unroll
    for (int s = 0; s < 8; s++) {
        a[s][0] = xs[arow * TXP + 8 * s + tig];
        a[s][1] = xs[(arow + 8) * TXP + 8 * s + tig];
        a[s][2] = xs[arow * TXP + 8 * s + tig + 4];
        a[s][3] = xs[(arow + 8) * TXP + 8 * s + tig + 4];
    }

    for (int pass = 0; pass < 5; pass++) {
        asm volatile("cp.async.wait_group 0;");
        __syncthreads();
        if (pass < 4) {
            unsigned* dstb = &wsb[((pass + 1) & 1) * 4096];
            unsigned sdst = (unsigned)__cvta_generic_to_shared(&dstb[t * 4]);
            const unsigned* gsrc = wfrag + (pass + 1) * 4096 + t * 4;
            #pragma unroll
            for (int c = 0; c < 4; c++) {
                asm volatile("cp.async.cg.shared.global [%0], [%1], 16;"
                             :: "r"(sdst + c * 4096), "l"(gsrc + c * 1024));
            }
            asm volatile("cp.async.commit_group;");
        }
        const unsigned* ws = &wsb[(pass & 1) * 4096];

        #pragma unroll
        for (int nt = 0; nt < 8; nt++) {
            float c0 = 0.f, c1 = 0.f, c2 = 0.f, c3 = 0.f;
            #pragma unroll
            for (int s = 0; s < 8; s++) {
                uint2 bb = *(const uint2*)&ws[((s * 8 + nt) << 6) + lane * 2];
                asm("mma.sync.aligned.m16n8k8.row.col.f32.tf32.tf32.f32 "
                    "{%0,%1,%2,%3}, {%4,%5,%6,%7}, {%8,%9}, {%0,%1,%2,%3};"
                    : "+f"(c0), "+f"(c1), "+f"(c2), "+f"(c3)
                    : "r"(a[s][0]), "r"(a[s][1]), "r"(a[s][2]), "r"(a[s][3]),
                      "r"(bb.x), "r"(bb.y));
            }
            int gr0 = r0 + arow, gr1 = gr0 + 8;
            int colo = pass * 64 + nt * 8 + 2 * tig;
            if (gr0 < N) *(float2*)&out[(size_t)gr0 * 320 + colo] = make_float2(c0, c1);
            if (gr1 < N) *(float2*)&out[(size_t)gr1 * 320 + colo] = make_float2(c2, c3);
        }
    }
}

// ---------------- RGCN gather: 16 lanes/node, direct byte offsets + fused combine/relu ----------------
extern "C" __global__ void k_rgcn_gather(const int* __restrict__ off, const int2* __restrict__ erec,
                                         const float* __restrict__ xt, const float* __restrict__ rdeg,
                                         float* __restrict__ h, int N) {
    int idx = blockIdx.x * blockDim.x + threadIdx.x;
    int node = idx >> 4;
    if (node >= N) return;
    unsigned lo = (unsigned)(idx & 15) << 4;
    int beg = __ldg(&off[node]), end = __ldg(&off[node + 1]);
    const char* xb = (const char*)xt;
    float4 a0 = {0,0,0,0}, a1 = {0,0,0,0}, a2 = {0,0,0,0}, a3 = {0,0,0,0};
    int i = beg;
    for (; i + 4 <= end; i += 4) {
        int2 r0 = __ldg(&erec[i]),     r1 = __ldg(&erec[i + 1]);
        int2 r2 = __ldg(&erec[i + 2]), r3 = __ldg(&erec[i + 3]);
        float4 v0 = __ldg((const float4*)(xb + ((unsigned)r0.x + lo)));
        float4 v1 = __ldg((const float4*)(xb + ((unsigned)r1.x + lo)));
        float4 v2 = __ldg((const float4*)(xb + ((unsigned)r2.x + lo)));
        float4 v3 = __ldg((const float4*)(xb + ((unsigned)r3.x + lo)));
        float w0 = __int_as_float(r0.y), w1 = __int_as_float(r1.y);
        float w2 = __int_as_float(r2.y), w3 = __int_as_float(r3.y);
        a0.x += w0*v0.x; a0.y += w0*v0.y; a0.z += w0*v0.z; a0.w += w0*v0.w;
        a1.x += w1*v1.x; a1.y += w1*v1.y; a1.z += w1*v1.z; a1.w += w1*v1.w;
        a2.x += w2*v2.x; a2.y += w2*v2.y; a2.z += w2*v2.z; a2.w += w2*v2.w;
        a3.x += w3*v3.x; a3.y += w3*v3.y; a3.z += w3*v3.z; a3.w += w3*v3.w;
    }
    for (; i < end; i++) {
        int2 r0 = __ldg(&erec[i]);
        float w0 = __int_as_float(r0.y);
        float4 v0 = __ldg((const float4*)(xb + ((unsigned)r0.x + lo)));
        a0.x += w0*v0.x; a0.y += w0*v0.y; a0.z += w0*v0.z; a0.w += w0*v0.w;
    }
    float4 s = __ldg((const float4*)(xb + ((unsigned)node * 1280u + lo)));
    float rd = __ldg(&rdeg[node]);
    float4 o;
    o.x = fmaxf((s.x + (a0.x + a1.x) + (a2.x + a3.x)) * rd, 0.f);
    o.y = fmaxf((s.y + (a0.y + a1.y) + (a2.y + a3.y)) * rd, 0.f);
    o.z = fmaxf((s.z + (a0.z + a1.z) + (a2.z + a3.z)) * rd, 0.f);
    o.w = fmaxf((s.w + (a0.w + a1.w) + (a2.w + a3.w)) * rd, 0.f);
    *(float4*)((char*)h + ((unsigned)node * 256u + lo)) = o;
}

// ---------------- FUSED group gather + combine (64-node tile) ----------------
// Phase 1: gather agg for 64 nodes directly into smem (k-major, rdeg applied).
// Phase 2: GEMM vs projW; epilogue h' = h + alpha*(gemm + b).
// HEAD=0: write h' to dst (h2 buffer; h itself untouched -> no cross-block race).
// HEAD=1: keep h' in smem, apply output head, write out.
template <int HEAD>
__device__ __forceinline__ void ggc_impl(
    const int* __restrict__ off, const int2* __restrict__ erec,
    const float* __restrict__ hin, const float* __restrict__ rdeg,
    const float* __restrict__ W, const float* __restrict__ b,
    const float* __restrict__ alpha_p,
    const float* __restrict__ outW, const float* __restrict__ outb,
    float* __restrict__ dst, int N) {
    extern __shared__ float sm[];
    float* xs = sm;                 // [64][68] k-major gemm input; HEAD reuses as xh [64][65]
    float* ws = sm + 64 * 68;       // [64][64] projW
    float* ws2 = ws + 64 * 64;      // [64][32] outW (HEAD only)
    int t = threadIdx.x;
    int r0 = blockIdx.x * 64;

    for (int i = t; i < 64 * 64; i += 256) ws[i] = W[i];
    if (HEAD) for (int i = t; i < 64 * 32; i += 256) ws2[i] = outW[i];

    // ---- phase 1: gather ----
    const char* hb = (const char*)hin;
    int lane = t & 15;
    unsigned lo = (unsigned)lane << 4;
    #pragma unroll
    for (int it = 0; it < 4; it++) {
        int nl = it * 16 + (t >> 4);
        int node = r0 + nl;
        float4 a0 = {0,0,0,0}, a1 = {0,0,0,0}, a2 = {0,0,0,0}, a3 = {0,0,0,0};
        float rd = 0.f;
        if (node < N) {
            rd = __ldg(&rdeg[node]);
            int beg = __ldg(&off[node]), end = __ldg(&off[node + 1]);
            int i = beg;
            for (; i + 4 <= end; i += 4) {
                int2 r0e = __ldg(&erec[i]),     r1e = __ldg(&erec[i + 1]);
                int2 r2e = __ldg(&erec[i + 2]), r3e = __ldg(&erec[i + 3]);
                float4 v0 = __ldg((const float4*)(hb + ((unsigned)r0e.x + lo)));
                float4 v1 = __ldg((const float4*)(hb + ((unsigned)r1e.x + lo)));
                float4 v2 = __ldg((const float4*)(hb + ((unsigned)r2e.x + lo)));
                float4 v3 = __ldg((const float4*)(hb + ((unsigned)r3e.x + lo)));
                float w0 = __int_as_float(r0e.y), w1 = __int_as_float(r1e.y);
                float w2 = __int_as_float(r2e.y), w3 = __int_as_float(r3e.y);
                a0.x += w0*v0.x; a0.y += w0*v0.y; a0.z += w0*v0.z; a0.w += w0*v0.w;
                a1.x += w1*v1.x; a1.y += w1*v1.y; a1.z += w1*v1.z; a1.w += w1*v1.w;
                a2.x += w2*v2.x; a2.y += w2*v2.y; a2.z += w2*v2.z; a2.w += w2*v2.w;
                a3.x += w3*v3.x; a3.y += w3*v3.y; a3.z += w3*v3.z; a3.w += w3*v3.w;
            }
            for (; i < end; i++) {
                int2 r0e = __ldg(&erec[i]);
                float w0 = __int_as_float(r0e.y);
                float4 v0 = __ldg((const float4*)(hb + ((unsigned)r0e.x + lo)));
                a0.x += w0*v0.x; a0.y += w0*v0.y; a0.z += w0*v0.z; a0.w += w0*v0.w;
            }
        }
        float ox = ((a0.x + a1.x) + (a2.x + a3.x)) * rd;
        float oy = ((a0.y + a1.y) + (a2.y + a3.y)) * rd;
        float oz = ((a0.z + a1.z) + (a2.z + a3.z)) * rd;
        float ow = ((a0.w + a1.w) + (a2.w + a3.w)) * rd;
        float* p = &xs[(4 * lane) * 68 + nl];
        p[0] = ox; p[68] = oy; p[136] = oz; p[204] = ow;
    }
    __syncthreads();

    // ---- phase 2: GEMM (2 rows x 8 cols per thread) ----
    float alpha = *alpha_p;
    int tx = t & 7, ty = t >> 3;   // ty 0..31
    const float* xp = &xs[2 * ty];

    unsigned long long acc[2][4];
    #pragma unroll
    for (int r = 0; r < 2; r++)
        #pragma unroll
        for (int j = 0; j < 4; j++) acc[r][j] = 0ULL;

    #pragma unroll 4
    for (int k = 0; k < 64; k++) {
        float2 xv = *(const float2*)&xp[k * 68];
        ulonglong2 wA = *(const ulonglong2*)&ws[k * 64 + 8 * tx];
        ulonglong2 wB = *(const ulonglong2*)&ws[k * 64 + 8 * tx + 4];
        unsigned long long x0 = pack2(xv.x), x1 = pack2(xv.y);
        fma2(acc[0][0], x0, wA.x); fma2(acc[0][1], x0, wA.y);
        fma2(acc[0][2], x0, wB.x); fma2(acc[0][3], x0, wB.y);
        fma2(acc[1][0], x1, wA.x); fma2(acc[1][1], x1, wA.y);
        fma2(acc[1][2], x1, wB.x); fma2(acc[1][3], x1, wB.y);
    }
    if (HEAD) __syncthreads();   // xs reads done before reuse as xh

    float4 b0 = *(const float4*)&b[8 * tx];
    float4 b1 = *(const float4*)&b[8 * tx + 4];
    #pragma unroll
    for (int r = 0; r < 2; r++) {
        int gr = r0 + 2 * ty + r;
        if (gr < N) {
            const float* hp = &hin[((size_t)gr << 6) + 8 * tx];
            float4 h0 = *(const float4*)hp;
            float4 h1 = *(const float4*)(hp + 4);
            float2 f0 = unpack2(acc[r][0]), f1 = unpack2(acc[r][1]);
            float2 f2 = unpack2(acc[r][2]), f3 = unpack2(acc[r][3]);
            h0.x += alpha * (f0.x + b0.x); h0.y += alpha * (f0.y + b0.y);
            h0.z += alpha * (f1.x + b0.z); h0.w += alpha * (f1.y + b0.w);
            h1.x += alpha * (f2.x + b1.x); h1.y += alpha * (f2.y + b1.y);
            h1.z += alpha * (f3.x + b1.z); h1.w += alpha * (f3.y + b1.w);
            if (HEAD) {
                float* xh = &xs[(2 * ty + r) * 65 + 8 * tx];
                xh[0] = h0.x; xh[1] = h0.y; xh[2] = h0.z; xh[3] = h0.w;
                xh[4] = h1.x; xh[5] = h1.y; xh[6] = h1.z; xh[7] = h1.w;
            } else {
                float* dp = &dst[((size_t)gr << 6) + 8 * tx];
                *(float4*)dp = h0;
                *(float4*)(dp + 4) = h1;
            }
        } else if (HEAD) {
            float* xh = &xs[(2 * ty + r) * 65 + 8 * tx];
            #pragma unroll
            for (int q = 0; q < 8; q++) xh[q] = 0.f;
        }
    }

    if (HEAD) {
        __syncthreads();
        int row = t & 63, th = t >> 6;   // th 0..3 -> 4 col groups of 8 = 32 cols
        int gr = r0 + row;
        int jl = th * 8;
        const float* xrow = &xs[row * 65];
        unsigned long long a0 = 0, a1 = 0, a2 = 0, a3 = 0;
        #pragma unroll
        for (int k = 0; k < 64; k++) {
            unsigned long long xv = pack2(xrow[k]);
            const float* wp = &ws2[k * 32 + jl];
            ulonglong2 wA = *(const ulonglong2*)wp;
            ulonglong2 wB = *(const ulonglong2*)(wp + 4);
            fma2(a0, xv, wA.x); fma2(a1, xv, wA.y);
            fma2(a2, xv, wB.x); fma2(a3, xv, wB.y);
        }
        if (gr < N) {
            float2 f0 = unpack2(a0), f1 = unpack2(a1), f2 = unpack2(a2), f3 = unpack2(a3);
            const float* bp = &outb[jl];
            float* op = &dst[(size_t)gr * 32 + jl];
            op[0] = f0.x + bp[0]; op[1] = f0.y + bp[1];
            op[2] = f1.x + bp[2]; op[3] = f1.y + bp[3];
            op[4] = f2.x + bp[4]; op[5] = f2.y + bp[5];
            op[6] = f3.x + bp[6]; op[7] = f3.y + bp[7];
        }
    }
}

extern "C" __global__ void __launch_bounds__(256)
k_ggc(const int* off, const int2* erec, const float* hin, const float* rdeg,
      const float* W, const float* b, const float* alpha_p, float* dst, int N) {
    ggc_impl<0>(off, erec, hin, rdeg, W, b, alpha_p, nullptr, nullptr, dst, N);
}
extern "C" __global__ void __launch_bounds__(256)
k_ggc_head(const int* off, const int2* erec, const float* hin, const float* rdeg,
           const float* W, const float* b, const float* alpha_p,
           const float* outW, const float* outb, float* out, int N) {
    ggc_impl<1>(off, erec, hin, rdeg, W, b, alpha_p, outW, outb, out, N);
}

// ---------------- launch ----------------
extern "C" void kernel_launch(void* const* d_in, const int* in_sizes, int n_in,
                              void* d_out, int out_size) {
    const float* x      = (const float*)d_in[0];
    const int*   ei     = (const int*)d_in[1];
    const int*   et     = (const int*)d_in[2];
    const float* ew     = (const float*)d_in[3];
    const float* W1     = (const float*)d_in[4];
    const float* W01    = (const float*)d_in[5];
    const float* alpha1 = (const float*)d_in[6];
    const float* projW1 = (const float*)d_in[7];
    const float* projb1 = (const float*)d_in[8];
    const float* W2     = (const float*)d_in[9];
    const float* W02    = (const float*)d_in[10];
    const float* alpha2 = (const float*)d_in[11];
    const float* projW2 = (const float*)d_in[12];
    const float* projb2 = (const float*)d_in[13];
    const float* outW   = (const float*)d_in[14];
    const float* outb   = (const float*)d_in[15];

    int N = in_sizes[0] / 64;
    int E = in_sizes[2];

    float *rdeg, *xt, *h, *h2;
    int *cntflag, *pref, *off, *cursor;
    int2 *erecR, *erecG;
    unsigned *wfrag;
    cudaGetSymbolAddress((void**)&cntflag, g_cntflag);
    cudaGetSymbolAddress((void**)&pref,    g_pref);
    cudaGetSymbolAddress((void**)&off,     g_off);
    cudaGetSymbolAddress((void**)&cursor,  g_cursor);
    cudaGetSymbolAddress((void**)&rdeg,    g_rdeg);
    cudaGetSymbolAddress((void**)&erecR,   g_erecR);
    cudaGetSymbolAddress((void**)&erecG,   g_erecG);
    cudaGetSymbolAddress((void**)&xt,      g_xt);
    cudaGetSymbolAddress((void**)&h,       g_h);
    cudaGetSymbolAddress((void**)&h2,      g_h2);
    cudaGetSymbolAddress((void**)&wfrag,   g_wfrag);

    static cudaStream_t s2 = nullptr;
    static cudaEvent_t evFork = nullptr, evJoin = nullptr;
    if (s2 == nullptr) {
        cudaStreamCreateWithFlags(&s2, cudaStreamNonBlocking);
        cudaEventCreateWithFlags(&evFork, cudaEventDisableTiming);
        cudaEventCreateWithFlags(&evJoin, cudaEventDisableTiming);
    }

    const int SMEM_M  = (128 * TXP + 2 * 4096) * 4;            // transform: 67584
    const int SMEM_G1 = (64 * 68 + 64 * 64) * 4;               // ggc: 33792
    const int SMEM_G2 = (64 * 68 + 64 * 64 + 64 * 32) * 4;     // ggc_head: 41984
    cudaFuncSetAttribute(k_transform_mma, cudaFuncAttributeMaxDynamicSharedMemorySize, SMEM_M);
    cudaFuncSetAttribute(k_ggc,           cudaFuncAttributeMaxDynamicSharedMemorySize, SMEM_G1);
    cudaFuncSetAttribute(k_ggc_head,      cudaFuncAttributeMaxDynamicSharedMemorySize, SMEM_G2);

    int ebl  = (E + 255) / 256;
    int e2bl = (E / 2 + 255) / 256;
    int gthr = (N * 16 + 255) / 256;
    int gbl  = (N + 127) / 128;
    int gbl2 = (N + 63) / 64;
    int B1   = (N + 1023) / 1024;

    // ---- fork: CSR on s2, wprep + transform L1 on main ----
    cudaEventRecord(evFork, 0);
    cudaStreamWaitEvent(s2, evFork, 0);

    k_deg<<<e2bl, 256, 0, s2>>>(ei, cntflag, E);
    k_wprep<<<160, 256>>>(W01, W1, W02, W2, wfrag);
    k_scanAll<<<B1, 1024, 0, s2>>>(cntflag, cntflag + NMAX, pref,
                                   off, cursor, rdeg, N, E);
    k_transform_mma<<<gbl, 256, SMEM_M>>>(x, wfrag, xt, N);
    k_fill<<<ebl, 256, 0, s2>>>(ei, et, ew, cursor, erecR, erecG, cntflag, E);
    cudaEventRecord(evJoin, s2);
    cudaStreamWaitEvent(0, evJoin, 0);

    // ---- layer 1 ----
    k_rgcn_gather<<<gthr, 256>>>(off, erecR, xt, rdeg, h, N);
    k_ggc<<<gbl2, 256, SMEM_G1>>>(off, erecG, h, rdeg, projW1, projb1, alpha1, h2, N);

    // ---- layer 2 ----
    k_transform_mma<<<gbl, 256, SMEM_M>>>(h2, wfrag + 20480, xt, N);
    k_rgcn_gather<<<gthr, 256>>>(off, erecR, xt, rdeg, h, N);
    k_ggc_head<<<gbl2, 256, SMEM_G2>>>(off, erecG, h, rdeg, projW2, projb2, alpha2,
                                       outW, outb, (float*)d_out, N);
}

// round 16
// speedup vs baseline: 1.1143x; 1.1143x over previous
#include <cuda_runtime.h>
#include <cstdint>

#define NMAX 50000
#define EMAX 1000000
#define XS_P 132
#define TXP 68     // A-tile smem pitch (tf32 words)

// ---------------- scratch (static device globals; no allocation) ----------------
__device__ int      g_cntflag[NMAX + 64];        // deg counts + scan flags (re-zeroed by k_fill)
__device__ int      g_pref[64];
__device__ int      g_off[NMAX + 1];
__device__ int      g_cursor[NMAX];
__device__ float    g_rdeg[NMAX];
__device__ int2     g_erecR[EMAX];               // {src*1280 + (rel+1)*256, w_bits}  (xt byte offset)
__device__ int2     g_erecG[EMAX];               // {src*256, w_bits}                 (h byte offset)
__device__ float    g_xt[(size_t)NMAX * 320];    // fp32 transformed feats [W0 | Wr0..Wr3]
__device__ float    g_h[(size_t)NMAX * 64];      // fp32 hidden state
__device__ float    g_agg[(size_t)NMAX * 64];    // fp32 group aggregation
__device__ unsigned g_wfrag[2 * 5 * 4096];       // tf32 frag-major weights (dense), both layers

// ---------------- packed fp32x2 helpers ----------------
__device__ __forceinline__ void fma2(unsigned long long &a, unsigned long long x, unsigned long long w) {
    asm("fma.rn.f32x2 %0, %1, %2, %0;" : "+l"(a) : "l"(x), "l"(w));
}
__device__ __forceinline__ unsigned long long pack2(float v) {
    unsigned long long r;
    asm("mov.b64 %0, {%1, %1};" : "=l"(r) : "f"(v));
    return r;
}
__device__ __forceinline__ float2 unpack2(unsigned long long a) {
    float2 f;
    asm("mov.b64 {%0, %1}, %2;" : "=f"(f.x), "=f"(f.y) : "l"(a));
    return f;
}
__device__ __forceinline__ unsigned f2tf32(float v) {
    unsigned r;
    asm("cvt.rna.tf32.f32 %0, %1;" : "=r"(r) : "f"(v));
    return r;
}

// ---------------- weight pre-conversion: fp32 [64][64] -> tf32 frag-major (dense) ----------------
extern "C" __global__ void k_wprep(const float* __restrict__ W01, const float* __restrict__ W1,
                                   const float* __restrict__ W02, const float* __restrict__ W2,
                                   unsigned* __restrict__ wfrag) {
    int i = blockIdx.x * blockDim.x + threadIdx.x;
    if (i >= 2 * 5 * 4096) return;
    int L = i / 20480;
    int rem = i - L * 20480;
    int p = rem >> 12, j = rem & 4095;
    const float* W0 = L ? W02 : W01;
    const float* Wr = L ? W2 : W1;
    float v = (p == 0) ? W0[j] : Wr[(p - 1) * 4096 + j];
    int k = j >> 6, n = j & 63;
    int s = k >> 3, kr = k & 7;
    int tig = kr & 3, c = kr >> 2;
    int nt = n >> 3, gid = n & 7;
    int lane = gid * 4 + tig;
    int dst = ((s * 8 + nt) << 6) + (lane << 1) + c;
    wfrag[L * 20480 + (p << 12) + dst] = f2tf32(v);
}

// ---------------- degree (2 edges/thread) ----------------
extern "C" __global__ void k_deg(const int* __restrict__ ei, int* __restrict__ cnt, int E) {
    int e2 = blockIdx.x * blockDim.x + threadIdx.x;
    int e = e2 * 2;
    if (e < E) {
        int2 d = *(const int2*)&ei[E + e];
        atomicAdd(&cnt[d.x], 1);
        if (e + 1 < E) atomicAdd(&cnt[d.y], 1);
    }
}

// ---------------- single-pass chained scan ----------------
extern "C" __global__ void __launch_bounds__(1024)
k_scanAll(const int* __restrict__ cnt, int* __restrict__ flag, int* __restrict__ pref,
          int* __restrict__ off, int* __restrict__ cursor, float* __restrict__ rdeg,
          int N, int E) {
    __shared__ int wsum[32];
    __shared__ int s_pref;
    int t = threadIdx.x, b = blockIdx.x, g = b * 1024 + t;
    int v = (g < N) ? cnt[g] : 0;
    int lane = t & 31, wid = t >> 5;
    int x = v;
    #pragma unroll
    for (int d = 1; d < 32; d <<= 1) {
        int y = __shfl_up_sync(0xFFFFFFFF, x, d);
        if (lane >= d) x += y;
    }
    if (lane == 31) wsum[wid] = x;
    __syncthreads();
    if (wid == 0) {
        int s = wsum[lane];
        #pragma unroll
        for (int d = 1; d < 32; d <<= 1) {
            int y = __shfl_up_sync(0xFFFFFFFF, s, d);
            if (lane >= d) s += y;
        }
        wsum[lane] = s;
    }
    __syncthreads();
    int incl = x + (wid > 0 ? wsum[wid - 1] : 0);
    if (t == 0) {
        int p = 0;
        if (b > 0) {
            while (atomicAdd(&flag[b - 1], 0) == 0) __nanosleep(40);
            __threadfence();
            p = pref[b - 1];
        }
        s_pref = p;
        pref[b] = p + wsum[31];
        __threadfence();
        atomicExch(&flag[b], 1);
    }
    __syncthreads();
    int base = s_pref;
    if (g < N) {
        int o = base + incl - v;
        off[g] = o;
        cursor[g] = o;
        rdeg[g] = 1.0f / (float)max(v, 1);
    }
    if (g == 0) off[N] = E;
}

// fill CSR edge records (both variants); re-zero cnt+flags for next replay
extern "C" __global__ void k_fill(const int* __restrict__ ei, const int* __restrict__ et,
                                  const float* __restrict__ ew, int* __restrict__ cursor,
                                  int2* __restrict__ erecR, int2* __restrict__ erecG,
                                  int* __restrict__ cntflag, int E) {
    int e = blockIdx.x * blockDim.x + threadIdx.x;
    if (e < NMAX + 64) cntflag[e] = 0;
    if (e >= E) return;
    int dst = ei[E + e];
    int s = ei[e];
    int wb = __float_as_int(ew[e]);
    int pos = atomicAdd(&cursor[dst], 1);
    erecR[pos] = make_int2(s * 1280 + ((et[e] + 1) << 8), wb);
    erecG[pos] = make_int2(s << 8, wb);
}

// ---------------- transform (tf32 mma, cp.async double-buffered dense frag-major W) ----------------
extern "C" __global__ void __launch_bounds__(256)
k_transform_mma(const float* __restrict__ A, const unsigned* __restrict__ wfrag,
                float* __restrict__ out, int N) {
    extern __shared__ unsigned usm[];
    unsigned* xs = usm;               // [128][TXP]
    unsigned* wsb = usm + 128 * TXP;  // 2 x 4096
    int t = threadIdx.x;
    int r0 = blockIdx.x * 128;

    {
        unsigned sdst = (unsigned)__cvta_generic_to_shared(&wsb[t * 4]);
        const unsigned* gsrc = wfrag + t * 4;
        #pragma unroll
        for (int c = 0; c < 4; c++) {
            asm volatile("cp.async.cg.shared.global [%0], [%1], 16;"
                         :: "r"(sdst + c * 4096), "l"(gsrc + c * 1024));
        }
        asm volatile("cp.async.commit_group;");
    }

    for (int i = t; i < 128 * 16; i += 256) {
        int row = i >> 4, c4 = (i & 15) << 2;
        int g = r0 + row;
        float4 v = {0.f, 0.f, 0.f, 0.f};
        if (g < N) v = *(const float4*)&A[(size_t)g * 64 + c4];
        uint4 o;
        o.x = f2tf32(v.x); o.y = f2tf32(v.y); o.z = f2tf32(v.z); o.w = f2tf32(v.w);
        *(uint4*)&xs[row * TXP + c4] = o;
    }
    __syncthreads();

    int w = t >> 5, lane = t & 31;
    int gid = lane >> 2, tig = lane & 3;
    int arow = 16 * w + gid;

    unsigned a[8][4];
    #pragma unroll
    for (int s = 0; s < 8; s++) {
        a[s][0] = xs[arow * TXP + 8 * s + tig];
        a[s][1] = xs[(arow + 8) * TXP + 8 * s + tig];
        a[s][2] = xs[arow * TXP + 8 * s + tig + 4];
        a[s][3] = xs[(arow + 8) * TXP + 8 * s + tig + 4];
    }

    for (int pass = 0; pass < 5; pass++) {
        asm volatile("cp.async.wait_group 0;");
        __syncthreads();
        if (pass < 4) {
            unsigned* dstb = &wsb[((pass + 1) & 1) * 4096];
            unsigned sdst = (unsigned)__cvta_generic_to_shared(&dstb[t * 4]);
            const unsigned* gsrc = wfrag + (pass + 1) * 4096 + t * 4;
            #pragma unroll
            for (int c = 0; c < 4; c++) {
                asm volatile("cp.async.cg.shared.global [%0], [%1], 16;"
                             :: "r"(sdst + c * 4096), "l"(gsrc + c * 1024));
            }
            asm volatile("cp.async.commit_group;");
        }
        const unsigned* ws = &wsb[(pass & 1) * 4096];

        #pragma unroll
        for (int nt = 0; nt < 8; nt++) {
            float c0 = 0.f, c1 = 0.f, c2 = 0.f, c3 = 0.f;
            #pragma unroll
            for (int s = 0; s < 8; s++) {
                uint2 bb = *(const uint2*)&ws[((s * 8 + nt) << 6) + lane * 2];
                asm("mma.sync.aligned.m16n8k8.row.col.f32.tf32.tf32.f32 "
                    "{%0,%1,%2,%3}, {%4,%5,%6,%7}, {%8,%9}, {%0,%1,%2,%3};"
                    : "+f"(c0), "+f"(c1), "+f"(c2), "+f"(c3)
                    : "r"(a[s][0]), "r"(a[s][1]), "r"(a[s][2]), "r"(a[s][3]),
                      "r"(bb.x), "r"(bb.y));
            }
            int gr0 = r0 + arow, gr1 = gr0 + 8;
            int colo = pass * 64 + nt * 8 + 2 * tig;
            if (gr0 < N) *(float2*)&out[(size_t)gr0 * 320 + colo] = make_float2(c0, c1);
            if (gr1 < N) *(float2*)&out[(size_t)gr1 * 320 + colo] = make_float2(c2, c3);
        }
    }
}

// ---------------- RGCN gather: 16 lanes/node, direct byte offsets + fused combine/relu ----------------
extern "C" __global__ void k_rgcn_gather(const int* __restrict__ off, const int2* __restrict__ erec,
                                         const float* __restrict__ xt, const float* __restrict__ rdeg,
                                         float* __restrict__ h, int N) {
    int idx = blockIdx.x * blockDim.x + threadIdx.x;
    int node = idx >> 4;
    if (node >= N) return;
    unsigned lo = (unsigned)(idx & 15) << 4;
    int beg = __ldg(&off[node]), end = __ldg(&off[node + 1]);
    const char* xb = (const char*)xt;
    float4 a0 = {0,0,0,0}, a1 = {0,0,0,0}, a2 = {0,0,0,0}, a3 = {0,0,0,0};
    int i = beg;
    for (; i + 4 <= end; i += 4) {
        int2 r0 = __ldg(&erec[i]),     r1 = __ldg(&erec[i + 1]);
        int2 r2 = __ldg(&erec[i + 2]), r3 = __ldg(&erec[i + 3]);
        float4 v0 = __ldg((const float4*)(xb + ((unsigned)r0.x + lo)));
        float4 v1 = __ldg((const float4*)(xb + ((unsigned)r1.x + lo)));
        float4 v2 = __ldg((const float4*)(xb + ((unsigned)r2.x + lo)));
        float4 v3 = __ldg((const float4*)(xb + ((unsigned)r3.x + lo)));
        float w0 = __int_as_float(r0.y), w1 = __int_as_float(r1.y);
        float w2 = __int_as_float(r2.y), w3 = __int_as_float(r3.y);
        a0.x += w0*v0.x; a0.y += w0*v0.y; a0.z += w0*v0.z; a0.w += w0*v0.w;
        a1.x += w1*v1.x; a1.y += w1*v1.y; a1.z += w1*v1.z; a1.w += w1*v1.w;
        a2.x += w2*v2.x; a2.y += w2*v2.y; a2.z += w2*v2.z; a2.w += w2*v2.w;
        a3.x += w3*v3.x; a3.y += w3*v3.y; a3.z += w3*v3.z; a3.w += w3*v3.w;
    }
    for (; i < end; i++) {
        int2 r0 = __ldg(&erec[i]);
        float w0 = __int_as_float(r0.y);
        float4 v0 = __ldg((const float4*)(xb + ((unsigned)r0.x + lo)));
        a0.x += w0*v0.x; a0.y += w0*v0.y; a0.z += w0*v0.z; a0.w += w0*v0.w;
    }
    float4 s = __ldg((const float4*)(xb + ((unsigned)node * 1280u + lo)));
    float rd = __ldg(&rdeg[node]);
    float4 o;
    o.x = fmaxf((s.x + (a0.x + a1.x) + (a2.x + a3.x)) * rd, 0.f);
    o.y = fmaxf((s.y + (a0.y + a1.y) + (a2.y + a3.y)) * rd, 0.f);
    o.z = fmaxf((s.z + (a0.z + a1.z) + (a2.z + a3.z)) * rd, 0.f);
    o.w = fmaxf((s.w + (a0.w + a1.w) + (a2.w + a3.w)) * rd, 0.f);
    *(float4*)((char*)h + ((unsigned)node * 256u + lo)) = o;
}

// ---------------- Group gather: 16 lanes/node, direct byte offsets ----------------
extern "C" __global__ void k_group_gather(const int* __restrict__ off, const int2* __restrict__ erec,
                                          const float* __restrict__ h, float* __restrict__ agg, int N) {
    int idx = blockIdx.x * blockDim.x + threadIdx.x;
    int node = idx >> 4;
    if (node >= N) return;
    unsigned lo = (unsigned)(idx & 15) << 4;
    int beg = __ldg(&off[node]), end = __ldg(&off[node + 1]);
    const char* hb = (const char*)h;
    float4 a0 = {0,0,0,0}, a1 = {0,0,0,0}, a2 = {0,0,0,0}, a3 = {0,0,0,0};
    int i = beg;
    for (; i + 4 <= end; i += 4) {
        int2 r0 = __ldg(&erec[i]),     r1 = __ldg(&erec[i + 1]);
        int2 r2 = __ldg(&erec[i + 2]), r3 = __ldg(&erec[i + 3]);
        float4 v0 = __ldg((const float4*)(hb + ((unsigned)r0.x + lo)));
        float4 v1 = __ldg((const float4*)(hb + ((unsigned)r1.x + lo)));
        float4 v2 = __ldg((const float4*)(hb + ((unsigned)r2.x + lo)));
        float4 v3 = __ldg((const float4*)(hb + ((unsigned)r3.x + lo)));
        float w0 = __int_as_float(r0.y), w1 = __int_as_float(r1.y);
        float w2 = __int_as_float(r2.y), w3 = __int_as_float(r3.y);
        a0.x += w0*v0.x; a0.y += w0*v0.y; a0.z += w0*v0.z; a0.w += w0*v0.w;
        a1.x += w1*v1.x; a1.y += w1*v1.y; a1.z += w1*v1.z; a1.w += w1*v1.w;
        a2.x += w2*v2.x; a2.y += w2*v2.y; a2.z += w2*v2.z; a2.w += w2*v2.w;
        a3.x += w3*v3.x; a3.y += w3*v3.y; a3.z += w3*v3.z; a3.w += w3*v3.w;
    }
    for (; i < end; i++) {
        int2 r0 = __ldg(&erec[i]);
        float w0 = __int_as_float(r0.y);
        float4 v0 = __ldg((const float4*)(hb + ((unsigned)r0.x + lo)));
        a0.x += w0*v0.x; a0.y += w0*v0.y; a0.z += w0*v0.z; a0.w += w0*v0.w;
    }
    float4 o;
    o.x = (a0.x + a1.x) + (a2.x + a3.x);
    o.y = (a0.y + a1.y) + (a2.y + a3.y);
    o.z = (a0.z + a1.z) + (a2.z + a3.z);
    o.w = (a0.w + a1.w) + (a2.w + a3.w);
    *(float4*)((char*)agg + ((unsigned)node * 256u + lo)) = o;
}

// ---------------- Group combine core ----------------
template <int HEAD>
__device__ __forceinline__ void group_combine_impl(
    const float* __restrict__ agg, const float* __restrict__ rdeg,
    const float* __restrict__ W, const float* __restrict__ b,
    const float* __restrict__ alpha_p, float* __restrict__ h,
    const float* __restrict__ outW, const float* __restrict__ outb,
    float* __restrict__ out, int N) {
    extern __shared__ float sm[];
    float* xs = sm;                      // [64][XS_P]; reused as xh [128][65] in HEAD phase
    float* ws = sm + 64 * XS_P;          // [64][64]
    float* ws2 = ws + 64 * 64;           // [64][32] (HEAD only)
    int t = threadIdx.x;
    int r0 = blockIdx.x * 128;

    for (int i = t; i < 128 * 64; i += 256) {
        int row = i >> 6, k = i & 63;
        int g = r0 + row;
        xs[k * XS_P + row] = (g < N) ? agg[(size_t)g * 64 + k] * rdeg[g] : 0.f;
    }
    for (int i = t; i < 64 * 64; i += 256) ws[i] = W[i];
    if (HEAD) for (int i = t; i < 64 * 32; i += 256) ws2[i] = outW[i];
    __syncthreads();

    float alpha = *alpha_p;
    int tx = t & 7, ty = t >> 3;
    const float* xp = &xs[4 * ty];

    unsigned long long acc[4][4];
    #pragma unroll
    for (int r = 0; r < 4; r++)
        #pragma unroll
        for (int j = 0; j < 4; j++) acc[r][j] = 0ULL;

    #pragma unroll 4
    for (int k = 0; k < 64; k++) {
        float4 xv = *(const float4*)&xp[k * XS_P];
        ulonglong2 wA = *(const ulonglong2*)&ws[k * 64 + 8 * tx];
        ulonglong2 wB = *(const ulonglong2*)&ws[k * 64 + 8 * tx + 4];
        unsigned long long x0 = pack2(xv.x), x1 = pack2(xv.y),
                           x2 = pack2(xv.z), x3 = pack2(xv.w);
        fma2(acc[0][0], x0, wA.x); fma2(acc[0][1], x0, wA.y);
        fma2(acc[0][2], x0, wB.x); fma2(acc[0][3], x0, wB.y);
        fma2(acc[1][0], x1, wA.x); fma2(acc[1][1], x1, wA.y);
        fma2(acc[1][2], x1, wB.x); fma2(acc[1][3], x1, wB.y);
        fma2(acc[2][0], x2, wA.x); fma2(acc[2][1], x2, wA.y);
        fma2(acc[2][2], x2, wB.x); fma2(acc[2][3], x2, wB.y);
        fma2(acc[3][0], x3, wA.x); fma2(acc[3][1], x3, wA.y);
        fma2(acc[3][2], x3, wB.x); fma2(acc[3][3], x3, wB.y);
    }
    if (HEAD) __syncthreads();

    float4 b0 = *(const float4*)&b[8 * tx];
    float4 b1 = *(const float4*)&b[8 * tx + 4];
    #pragma unroll
    for (int r = 0; r < 4; r++) {
        int gr = r0 + 4 * ty + r;
        if (gr < N) {
            float* hp = &h[((size_t)gr << 6) + 8 * tx];
            float4 h0 = *(float4*)hp;
            float4 h1 = *(float4*)(hp + 4);
            float2 f0 = unpack2(acc[r][0]), f1 = unpack2(acc[r][1]);
            float2 f2 = unpack2(acc[r][2]), f3 = unpack2(acc[r][3]);
            h0.x += alpha * (f0.x + b0.x); h0.y += alpha * (f0.y + b0.y);
            h0.z += alpha * (f1.x + b0.z); h0.w += alpha * (f1.y + b0.w);
            h1.x += alpha * (f2.x + b1.x); h1.y += alpha * (f2.y + b1.y);
            h1.z += alpha * (f3.x + b1.z); h1.w += alpha * (f3.y + b1.w);
            if (HEAD) {
                float* xh = &xs[(4 * ty + r) * 65 + 8 * tx];
                xh[0] = h0.x; xh[1] = h0.y; xh[2] = h0.z; xh[3] = h0.w;
                xh[4] = h1.x; xh[5] = h1.y; xh[6] = h1.z; xh[7] = h1.w;
            } else {
                *(float4*)hp = h0;
                *(float4*)(hp + 4) = h1;
            }
        }
    }

    if (HEAD) {
        __syncthreads();
        int row = t & 127, th = t >> 7;
        int gr = r0 + row;
        const float* xrow = &xs[row * 65];
        for (int jt = 0; jt < 2; jt++) {
            int jl = (jt * 2 + th) * 8;
            unsigned long long a0 = 0, a1 = 0, a2 = 0, a3 = 0;
            #pragma unroll
            for (int k = 0; k < 64; k++) {
                unsigned long long xv = pack2(xrow[k]);
                const float* wp = &ws2[k * 32 + jl];
                ulonglong2 wA = *(const ulonglong2*)wp;
                ulonglong2 wB = *(const ulonglong2*)(wp + 4);
                fma2(a0, xv, wA.x); fma2(a1, xv, wA.y);
                fma2(a2, xv, wB.x); fma2(a3, xv, wB.y);
            }
            if (gr < N) {
                float2 f0 = unpack2(a0), f1 = unpack2(a1), f2 = unpack2(a2), f3 = unpack2(a3);
                const float* bp = &outb[jl];
                float* op = &out[(size_t)gr * 32 + jl];
                op[0] = f0.x + bp[0]; op[1] = f0.y + bp[1];
                op[2] = f1.x + bp[2]; op[3] = f1.y + bp[3];
                op[4] = f2.x + bp[4]; op[5] = f2.y + bp[5];
                op[6] = f3.x + bp[6]; op[7] = f3.y + bp[7];
            }
        }
    }
}

extern "C" __global__ void __launch_bounds__(256)
k_group_combine(const float* agg, const float* rdeg, const float* W, const float* b,
                const float* alpha_p, float* h, int N) {
    group_combine_impl<0>(agg, rdeg, W, b, alpha_p, h, nullptr, nullptr, nullptr, N);
}
extern "C" __global__ void __launch_bounds__(256)
k_group_combine_head(const float* agg, const float* rdeg, const float* W, const float* b,
                     const float* alpha_p, float* h, const float* outW, const float* outb,
                     float* out, int N) {
    group_combine_impl<1>(agg, rdeg, W, b, alpha_p, h, outW, outb, out, N);
}

// ---------------- launch ----------------
extern "C" void kernel_launch(void* const* d_in, const int* in_sizes, int n_in,
                              void* d_out, int out_size) {
    const float* x      = (const float*)d_in[0];
    const int*   ei     = (const int*)d_in[1];
    const int*   et     = (const int*)d_in[2];
    const float* ew     = (const float*)d_in[3];
    const float* W1     = (const float*)d_in[4];
    const float* W01    = (const float*)d_in[5];
    const float* alpha1 = (const float*)d_in[6];
    const float* projW1 = (const float*)d_in[7];
    const float* projb1 = (const float*)d_in[8];
    const float* W2     = (const float*)d_in[9];
    const float* W02    = (const float*)d_in[10];
    const float* alpha2 = (const float*)d_in[11];
    const float* projW2 = (const float*)d_in[12];
    const float* projb2 = (const float*)d_in[13];
    const float* outW   = (const float*)d_in[14];
    const float* outb   = (const float*)d_in[15];

    int N = in_sizes[0] / 64;
    int E = in_sizes[2];

    float *rdeg, *agg, *xt, *h;
    int *cntflag, *pref, *off, *cursor;
    int2 *erecR, *erecG;
    unsigned *wfrag;
    cudaGetSymbolAddress((void**)&cntflag, g_cntflag);
    cudaGetSymbolAddress((void**)&pref,    g_pref);
    cudaGetSymbolAddress((void**)&off,     g_off);
    cudaGetSymbolAddress((void**)&cursor,  g_cursor);
    cudaGetSymbolAddress((void**)&rdeg,    g_rdeg);
    cudaGetSymbolAddress((void**)&erecR,   g_erecR);
    cudaGetSymbolAddress((void**)&erecG,   g_erecG);
    cudaGetSymbolAddress((void**)&xt,      g_xt);
    cudaGetSymbolAddress((void**)&h,       g_h);
    cudaGetSymbolAddress((void**)&agg,     g_agg);
    cudaGetSymbolAddress((void**)&wfrag,   g_wfrag);

    static cudaStream_t s2 = nullptr;
    static cudaEvent_t evFork = nullptr, evJoin = nullptr;
    if (s2 == nullptr) {
        cudaStreamCreateWithFlags(&s2, cudaStreamNonBlocking);
        cudaEventCreateWithFlags(&evFork, cudaEventDisableTiming);
        cudaEventCreateWithFlags(&evJoin, cudaEventDisableTiming);
    }

    const int SMEM_M  = (128 * TXP + 2 * 4096) * 4;
    const int SMEM_T  = (64 * XS_P + 64 * 64) * 4;
    const int SMEM_TH = (64 * XS_P + 64 * 64 + 64 * 32) * 4;
    cudaFuncSetAttribute(k_transform_mma,      cudaFuncAttributeMaxDynamicSharedMemorySize, SMEM_M);
    cudaFuncSetAttribute(k_group_combine,      cudaFuncAttributeMaxDynamicSharedMemorySize, SMEM_T);
    cudaFuncSetAttribute(k_group_combine_head, cudaFuncAttributeMaxDynamicSharedMemorySize, SMEM_TH);

    int ebl  = (E + 255) / 256;
    int e2bl = (E / 2 + 255) / 256;
    int gthr = (N * 16 + 255) / 256;
    int gbl  = (N + 127) / 128;
    int B1   = (N + 1023) / 1024;

    // ---- fork: CSR on s2, wprep + transform L1 on main ----
    cudaEventRecord(evFork, 0);
    cudaStreamWaitEvent(s2, evFork, 0);

    k_deg<<<e2bl, 256, 0, s2>>>(ei, cntflag, E);
    k_wprep<<<160, 256>>>(W01, W1, W02, W2, wfrag);
    k_scanAll<<<B1, 1024, 0, s2>>>(cntflag, cntflag + NMAX, pref,
                                   off, cursor, rdeg, N, E);
    k_transform_mma<<<gbl, 256, SMEM_M>>>(x, wfrag, xt, N);
    k_fill<<<ebl, 256, 0, s2>>>(ei, et, ew, cursor, erecR, erecG, cntflag, E);
    cudaEventRecord(evJoin, s2);
    cudaStreamWaitEvent(0, evJoin, 0);

    // ---- layer 1 ----
    k_rgcn_gather<<<gthr, 256>>>(off, erecR, xt, rdeg, h, N);
    k_group_gather<<<gthr, 256>>>(off, erecG, h, agg, N);
    k_group_combine<<<gbl, 256, SMEM_T>>>(agg, rdeg, projW1, projb1, alpha1, h, N);

    // ---- layer 2 ----
    k_transform_mma<<<gbl, 256, SMEM_M>>>(h, wfrag + 20480, xt, N);
    k_rgcn_gather<<<gthr, 256>>>(off, erecR, xt, rdeg, h, N);
    k_group_gather<<<gthr, 256>>>(off, erecG, h, agg, N);
    k_group_combine_head<<<gbl, 256, SMEM_TH>>>(agg, rdeg, projW2, projb2, alpha2, h,
                                                outW, outb, (float*)d_out, N);
}